// round 2
// baseline (speedup 1.0000x reference)
#include <cuda_runtime.h>

#define NN 50000
#define NE 800000
#define D 128
#define OUTW (5 * D)   // 640

// ---- scratch (no allocations allowed; __device__ globals are the sanctioned path) ----
__device__ float g_deg[NN];        // degree, then dinv in-place
__device__ int   g_count[NN];      // in-degree edge counts
__device__ int   g_off[NN + 1];    // CSR offsets (exclusive scan of counts)
__device__ int   g_cursor[NN];     // scatter cursors
__device__ int   g_csr_row[NE];    // source node per CSR slot
__device__ float g_csr_w[NE];      // normalized weight per CSR slot
__device__ float g_gsum[D];        // global feature sum

// ---------------------------------------------------------------------------
__global__ void zero_kernel() {
    int i = blockIdx.x * blockDim.x + threadIdx.x;
    if (i < NN) { g_deg[i] = 0.0f; g_count[i] = 0; g_cursor[i] = 0; }
    if (i < D)  g_gsum[i] = 0.0f;
}

// deg[col] += w ; count[col]++   (edge_index is int32: JAX demotes int64 w/o x64)
__global__ void deg_kernel(const int* __restrict__ ei,
                           const float* __restrict__ ew) {
    int e = blockIdx.x * blockDim.x + threadIdx.x;
    if (e >= NE) return;
    int col = ei[NE + e];
    atomicAdd(&g_deg[col], ew[e]);
    atomicAdd(&g_count[col], 1);
}

__global__ void dinv_kernel() {
    int i = blockIdx.x * blockDim.x + threadIdx.x;
    if (i < NN) {
        float d = g_deg[i];
        g_deg[i] = (d > 0.0f) ? rsqrtf(d) : 0.0f;
    }
}

// single-block exclusive scan of g_count -> g_off (N=50000, ~49 chunks of 1024)
__global__ void scan_kernel() {
    __shared__ int temp[1024];
    __shared__ int carry;
    if (threadIdx.x == 0) carry = 0;
    __syncthreads();
    for (int base = 0; base < NN; base += 1024) {
        int i = base + threadIdx.x;
        int v = (i < NN) ? g_count[i] : 0;
        temp[threadIdx.x] = v;
        __syncthreads();
        for (int s = 1; s < 1024; s <<= 1) {
            int t = 0;
            if (threadIdx.x >= s) t = temp[threadIdx.x - s];
            __syncthreads();
            temp[threadIdx.x] += t;
            __syncthreads();
        }
        if (i < NN) g_off[i] = carry + temp[threadIdx.x] - v;  // exclusive
        __syncthreads();
        if (threadIdx.x == 1023) carry += temp[1023];
        __syncthreads();
    }
    if (threadIdx.x == 0) g_off[NN] = carry;
}

// scatter edges into CSR with precomputed normalized weight
__global__ void scatter_kernel(const int* __restrict__ ei,
                               const float* __restrict__ ew) {
    int e = blockIdx.x * blockDim.x + threadIdx.x;
    if (e >= NE) return;
    int row = ei[e];
    int col = ei[NE + e];
    float w = g_deg[row] * ew[e] * g_deg[col];
    int pos = g_off[col] + atomicAdd(&g_cursor[col], 1);
    g_csr_row[pos] = row;
    g_csr_w[pos]   = w;
}

// copy x into out[:, 0:128] and accumulate column sums for the mean
// block = 128 threads (one per feature), each block covers 64 rows
__global__ void copy_mean_kernel(const float* __restrict__ x, float* __restrict__ out) {
    int d  = threadIdx.x;
    int r0 = blockIdx.x * 64;
    int r1 = min(r0 + 64, NN);
    float s = 0.0f;
    for (int r = r0; r < r1; r++) {
        float v = x[r * D + d];
        out[(long long)r * OUTW + d] = v;
        s += v;
    }
    atomicAdd(&g_gsum[d], s);
}

// one block (128 threads) per destination node; gather over CSR edges.
// reads prev-hop slab at column in_off, writes slab at out_off (both inside out)
__global__ void hop_kernel(float* __restrict__ out, int in_off, int out_off) {
    __shared__ int   srow[128];
    __shared__ float sw[128];
    int i = blockIdx.x;
    int d = threadIdx.x;
    int start = g_off[i], end = g_off[i + 1];
    float acc = 0.0f;
    for (int cb = start; cb < end; cb += 128) {
        int ne = min(128, end - cb);
        if (d < ne) {
            srow[d] = g_csr_row[cb + d];
            sw[d]   = g_csr_w[cb + d];
        }
        __syncthreads();
        for (int e = 0; e < ne; e++) {
            acc += sw[e] * out[(long long)srow[e] * OUTW + in_off + d];
        }
        __syncthreads();
    }
    out[(long long)i * OUTW + out_off + d] = acc;
}

__global__ void bcast_kernel(float* __restrict__ out) {
    int i = blockIdx.x;
    int d = threadIdx.x;
    out[(long long)i * OUTW + 4 * D + d] = g_gsum[d] * (1.0f / (float)NN);
}

// ---------------------------------------------------------------------------
extern "C" void kernel_launch(void* const* d_in, const int* in_sizes, int n_in,
                              void* d_out, int out_size) {
    const float* x  = (const float*)d_in[0];
    const int*   ei = (const int*)d_in[1];
    const float* ew = (const float*)d_in[2];
    float* out = (float*)d_out;

    zero_kernel<<<(NN + 255) / 256, 256>>>();
    deg_kernel<<<(NE + 255) / 256, 256>>>(ei, ew);
    dinv_kernel<<<(NN + 255) / 256, 256>>>();
    scan_kernel<<<1, 1024>>>();
    scatter_kernel<<<(NE + 255) / 256, 256>>>(ei, ew);
    copy_mean_kernel<<<(NN + 63) / 64, 128>>>(x, out);

    hop_kernel<<<NN, 128>>>(out, 0 * D, 1 * D);
    hop_kernel<<<NN, 128>>>(out, 1 * D, 2 * D);
    hop_kernel<<<NN, 128>>>(out, 2 * D, 3 * D);

    bcast_kernel<<<NN, 128>>>(out);
}

// round 3
// speedup vs baseline: 1.1779x; 1.1779x over previous
#include <cuda_runtime.h>

#define NN 50000
#define NE 800000
#define D 128
#define OUTW (5 * D)     // 640 floats per output row
#define OUTW4 (OUTW / 4) // 160 float4 per output row

// ---- scratch (__device__ globals; no allocations allowed) ----
__device__ float              g_deg[NN];      // degree, then dinv in-place
__device__ int                g_count[NN];    // in-degree edge counts
__device__ int                g_off[NN + 1];  // CSR offsets
__device__ int                g_cursor[NN];   // scatter cursors
__device__ unsigned long long g_csr[NE];      // packed: (w_bits << 32) | (row * OUTW4)
__device__ float              g_gsum[D];      // global feature sum

// ---------------------------------------------------------------------------
__global__ void zero_kernel() {
    int i = blockIdx.x * blockDim.x + threadIdx.x;
    if (i < NN) { g_deg[i] = 0.0f; g_count[i] = 0; g_cursor[i] = 0; }
    if (i < D)  g_gsum[i] = 0.0f;
}

// edge_index is int32 (JAX demotes int64 without x64 flag)
__global__ void deg_kernel(const int* __restrict__ ei,
                           const float* __restrict__ ew) {
    int e = blockIdx.x * blockDim.x + threadIdx.x;
    if (e >= NE) return;
    int col = ei[NE + e];
    atomicAdd(&g_deg[col], ew[e]);
    atomicAdd(&g_count[col], 1);
}

__global__ void dinv_kernel() {
    int i = blockIdx.x * blockDim.x + threadIdx.x;
    if (i < NN) {
        float d = g_deg[i];
        g_deg[i] = (d > 0.0f) ? rsqrtf(d) : 0.0f;
    }
}

// thread-coarsened single-block exclusive scan: 1024 threads x 49 elements
__global__ void scan_kernel() {
    const int CH = 49;                    // 1024*49 = 50176 >= NN
    int tid  = threadIdx.x;
    int lane = tid & 31, wid = tid >> 5;
    int base = tid * CH;

    int local = 0;
    #pragma unroll 7
    for (int k = 0; k < CH; k++) {
        int i = base + k;
        if (i < NN) local += g_count[i];
    }
    // inclusive warp scan of per-thread sums
    int v = local;
    #pragma unroll
    for (int s = 1; s < 32; s <<= 1) {
        int t = __shfl_up_sync(0xffffffffu, v, s);
        if (lane >= s) v += t;
    }
    __shared__ int wsum[32];
    if (lane == 31) wsum[wid] = v;
    __syncthreads();
    if (wid == 0) {
        int t = wsum[lane];
        #pragma unroll
        for (int s = 1; s < 32; s <<= 1) {
            int u = __shfl_up_sync(0xffffffffu, t, s);
            if (lane >= s) t += u;
        }
        wsum[lane] = t;                   // inclusive warp totals
    }
    __syncthreads();
    int excl = v - local + (wid > 0 ? wsum[wid - 1] : 0);

    int running = excl;
    #pragma unroll 7
    for (int k = 0; k < CH; k++) {
        int i = base + k;
        if (i < NN) { g_off[i] = running; running += g_count[i]; }
    }
    if (tid == 1023) g_off[NN] = running; // == total (tail elements are all >= NN)
}

// scatter edges into CSR with precomputed normalized weight, packed 8B/edge
__global__ void scatter_kernel(const int* __restrict__ ei,
                               const float* __restrict__ ew) {
    int e = blockIdx.x * blockDim.x + threadIdx.x;
    if (e >= NE) return;
    int row = ei[e];
    int col = ei[NE + e];
    float w = g_deg[row] * ew[e] * g_deg[col];
    int pos = g_off[col] + atomicAdd(&g_cursor[col], 1);
    unsigned long long p =
        ((unsigned long long)__float_as_uint(w) << 32) |
        (unsigned int)(row * OUTW4);
    g_csr[pos] = p;
}

// copy x into out[:, 0:128] (float4) + accumulate column sums for the mean
// one warp per 256 rows; lane owns 4 features
__global__ void copy_mean_kernel(const float* __restrict__ x, float* __restrict__ out) {
    int lane = threadIdx.x & 31;
    int wrp  = (blockIdx.x * (blockDim.x >> 5)) + (threadIdx.x >> 5);
    int r0 = wrp * 256;
    if (r0 >= NN) return;
    int r1 = min(r0 + 256, NN);
    const float4* x4 = (const float4*)x;
    float4* out4 = (float4*)out;
    float4 s = make_float4(0.f, 0.f, 0.f, 0.f);
    for (int r = r0; r < r1; r++) {
        float4 v = x4[r * 32 + lane];
        out4[(long long)r * OUTW4 + lane] = v;
        s.x += v.x; s.y += v.y; s.z += v.z; s.w += v.w;
    }
    atomicAdd(&g_gsum[lane * 4 + 0], s.x);
    atomicAdd(&g_gsum[lane * 4 + 1], s.y);
    atomicAdd(&g_gsum[lane * 4 + 2], s.z);
    atomicAdd(&g_gsum[lane * 4 + 3], s.w);
}

// warp-per-node gather: broadcast LDG.64 of packed edge, gather LDG.128 of row
__global__ void hop_kernel(float* __restrict__ out, int in_off4, int out_off4) {
    int lane = threadIdx.x & 31;
    int node = (blockIdx.x * (blockDim.x >> 5)) + (threadIdx.x >> 5);
    if (node >= NN) return;
    int start = g_off[node], end = g_off[node + 1];
    const float4* in4 = ((const float4*)out) + in_off4;
    float4 acc = make_float4(0.f, 0.f, 0.f, 0.f);
    #pragma unroll 4
    for (int e = start; e < end; e++) {
        unsigned long long p = g_csr[e];          // uniform across warp (broadcast)
        int   radr = (int)(p & 0xffffffffu);      // row * OUTW4
        float w    = __uint_as_float((unsigned int)(p >> 32));
        float4 v = in4[radr + lane];
        acc.x += w * v.x; acc.y += w * v.y; acc.z += w * v.z; acc.w += w * v.w;
    }
    ((float4*)out)[(long long)node * OUTW4 + out_off4 + lane] = acc;
}

// broadcast mean into out[:, 4D:5D]
__global__ void bcast_kernel(float* __restrict__ out) {
    int lane = threadIdx.x & 31;
    int node = (blockIdx.x * (blockDim.x >> 5)) + (threadIdx.x >> 5);
    if (node >= NN) return;
    const float inv = 1.0f / (float)NN;
    float4 g = make_float4(g_gsum[lane * 4 + 0] * inv, g_gsum[lane * 4 + 1] * inv,
                           g_gsum[lane * 4 + 2] * inv, g_gsum[lane * 4 + 3] * inv);
    ((float4*)out)[(long long)node * OUTW4 + 4 * (D / 4) / 1 + lane - lane] = g; // placeholder
}

// NOTE: the expression above must write slab 4 (columns 512..639): index = node*160 + 128 + lane
__global__ void bcast_kernel_fixed(float* __restrict__ out) {
    int lane = threadIdx.x & 31;
    int node = (blockIdx.x * (blockDim.x >> 5)) + (threadIdx.x >> 5);
    if (node >= NN) return;
    const float inv = 1.0f / (float)NN;
    float4 g = make_float4(g_gsum[lane * 4 + 0] * inv, g_gsum[lane * 4 + 1] * inv,
                           g_gsum[lane * 4 + 2] * inv, g_gsum[lane * 4 + 3] * inv);
    ((float4*)out)[(long long)node * OUTW4 + 128 + lane] = g;
}

// ---------------------------------------------------------------------------
extern "C" void kernel_launch(void* const* d_in, const int* in_sizes, int n_in,
                              void* d_out, int out_size) {
    const float* x  = (const float*)d_in[0];
    const int*   ei = (const int*)d_in[1];
    const float* ew = (const float*)d_in[2];
    float* out = (float*)d_out;

    zero_kernel<<<(NN + 255) / 256, 256>>>();
    deg_kernel<<<(NE + 255) / 256, 256>>>(ei, ew);
    dinv_kernel<<<(NN + 255) / 256, 256>>>();
    scan_kernel<<<1, 1024>>>();
    scatter_kernel<<<(NE + 255) / 256, 256>>>(ei, ew);
    copy_mean_kernel<<<(196 + 7) / 8, 256>>>(x, out);   // 196 warps cover 50000 rows

    // warp per node: 8 warps/block -> 6250 blocks
    hop_kernel<<<(NN + 7) / 8, 256>>>(out,  0, 32);
    hop_kernel<<<(NN + 7) / 8, 256>>>(out, 32, 64);
    hop_kernel<<<(NN + 7) / 8, 256>>>(out, 64, 96);

    bcast_kernel_fixed<<<(NN + 7) / 8, 256>>>(out);
}

// round 4
// speedup vs baseline: 1.4135x; 1.2000x over previous
#include <cuda_runtime.h>

#define NN 50000
#define NE 800000
#define D 128
#define OUTW (5 * D)     // 640 floats per output row
#define OUTW4 (OUTW / 4) // 160 float4 per output row
#define NB 196           // scan blocks: 196*256 = 50176 >= NN

// ---- scratch (__device__ globals; no allocations allowed) ----
__device__ float              g_deg[NN];      // degree, then dinv in-place
__device__ int                g_count[NN];    // in-degree edge counts
__device__ int                g_off[NN + 1];  // CSR offsets
__device__ int                g_cursor[NN];   // scatter cursors
__device__ int                g_bsum[NB];     // per-block count sums (then exclusive-scanned)
__device__ unsigned long long g_csr[NE];      // packed: (w_bits << 32) | (row * OUTW4)
__device__ float              g_gsum[D];      // global feature sum

// ---------------------------------------------------------------------------
__global__ void zero_kernel() {
    int i = blockIdx.x * blockDim.x + threadIdx.x;
    if (i < NN) { g_deg[i] = 0.0f; g_count[i] = 0; g_cursor[i] = 0; }
    if (i < D)  g_gsum[i] = 0.0f;
}

// edge_index is int32 (JAX demotes int64 without x64 flag)
__global__ void deg_kernel(const int* __restrict__ ei,
                           const float* __restrict__ ew) {
    int e = blockIdx.x * blockDim.x + threadIdx.x;
    if (e >= NE) return;
    int col = ei[NE + e];
    atomicAdd(&g_deg[col], ew[e]);
    atomicAdd(&g_count[col], 1);
}

__global__ void dinv_kernel() {
    int i = blockIdx.x * blockDim.x + threadIdx.x;
    if (i < NN) {
        float d = g_deg[i];
        g_deg[i] = (d > 0.0f) ? rsqrtf(d) : 0.0f;
    }
}

// ---- 3-phase coalesced scan -----------------------------------------------
// phase 1: per-block (256 contiguous counts) reduction
__global__ void partial_kernel() {
    int i = blockIdx.x * 256 + threadIdx.x;
    int lane = threadIdx.x & 31, wid = threadIdx.x >> 5;
    int v = (i < NN) ? g_count[i] : 0;
    #pragma unroll
    for (int s = 16; s > 0; s >>= 1) v += __shfl_down_sync(0xffffffffu, v, s);
    __shared__ int ws[8];
    if (lane == 0) ws[wid] = v;
    __syncthreads();
    if (threadIdx.x == 0) {
        int t = 0;
        #pragma unroll
        for (int w = 0; w < 8; w++) t += ws[w];
        g_bsum[blockIdx.x] = t;
    }
}

// phase 2: exclusive scan of the NB block sums (one block, one warp-chain)
__global__ void bscan_kernel() {
    // 256 threads, NB=196 values: warp-scan + combine
    __shared__ int sh[NB];
    int tid = threadIdx.x;
    int v = (tid < NB) ? g_bsum[tid] : 0;
    int lane = tid & 31, wid = tid >> 5;
    int iv = v;
    #pragma unroll
    for (int s = 1; s < 32; s <<= 1) {
        int t = __shfl_up_sync(0xffffffffu, iv, s);
        if (lane >= s) iv += t;
    }
    __shared__ int wtot[8];
    if (lane == 31) wtot[wid] = iv;
    __syncthreads();
    if (wid == 0 && lane < 8) {
        int t = wtot[lane];
        #pragma unroll
        for (int s = 1; s < 8; s <<= 1) {
            int u = __shfl_up_sync(0xffu, t, s);
            if (lane >= s) t += u;
        }
        wtot[lane] = t;
    }
    __syncthreads();
    int excl = iv - v + (wid > 0 ? wtot[wid - 1] : 0);
    if (tid < NB) sh[tid] = excl;
    __syncthreads();
    if (tid < NB) g_bsum[tid] = sh[tid];
    if (tid == 0) g_off[NN] = NE;   // total in-degree = number of edges
}

// phase 3: per-block exclusive scan of 256 counts + block prefix -> g_off
__global__ void offsets_kernel() {
    int i = blockIdx.x * 256 + threadIdx.x;
    int lane = threadIdx.x & 31, wid = threadIdx.x >> 5;
    int v = (i < NN) ? g_count[i] : 0;
    int iv = v;
    #pragma unroll
    for (int s = 1; s < 32; s <<= 1) {
        int t = __shfl_up_sync(0xffffffffu, iv, s);
        if (lane >= s) iv += t;
    }
    __shared__ int wtot[8];
    if (lane == 31) wtot[wid] = iv;
    __syncthreads();
    if (wid == 0 && lane < 8) {
        int t = wtot[lane];
        #pragma unroll
        for (int s = 1; s < 8; s <<= 1) {
            int u = __shfl_up_sync(0xffu, t, s);
            if (lane >= s) t += u;
        }
        wtot[lane] = t;
    }
    __syncthreads();
    int excl = iv - v + (wid > 0 ? wtot[wid - 1] : 0) + g_bsum[blockIdx.x];
    if (i < NN) g_off[i] = excl;
}

// ---- CSR scatter -----------------------------------------------------------
__global__ void scatter_kernel(const int* __restrict__ ei,
                               const float* __restrict__ ew) {
    int e = blockIdx.x * blockDim.x + threadIdx.x;
    if (e >= NE) return;
    int row = ei[e];
    int col = ei[NE + e];
    float w = g_deg[row] * ew[e] * g_deg[col];
    int pos = g_off[col] + atomicAdd(&g_cursor[col], 1);
    unsigned long long p =
        ((unsigned long long)__float_as_uint(w) << 32) |
        (unsigned int)(row * OUTW4);
    g_csr[pos] = p;
}

// copy x into out[:, 0:128] (float4) + accumulate column sums for the mean
__global__ void copy_mean_kernel(const float* __restrict__ x, float* __restrict__ out) {
    int lane = threadIdx.x & 31;
    int wrp  = (blockIdx.x * (blockDim.x >> 5)) + (threadIdx.x >> 5);
    int r0 = wrp * 256;
    if (r0 >= NN) return;
    int r1 = min(r0 + 256, NN);
    const float4* x4 = (const float4*)x;
    float4* out4 = (float4*)out;
    float4 s = make_float4(0.f, 0.f, 0.f, 0.f);
    for (int r = r0; r < r1; r++) {
        float4 v = x4[r * 32 + lane];
        out4[(long long)r * OUTW4 + lane] = v;
        s.x += v.x; s.y += v.y; s.z += v.z; s.w += v.w;
    }
    atomicAdd(&g_gsum[lane * 4 + 0], s.x);
    atomicAdd(&g_gsum[lane * 4 + 1], s.y);
    atomicAdd(&g_gsum[lane * 4 + 2], s.z);
    atomicAdd(&g_gsum[lane * 4 + 3], s.w);
}

// warp-per-node gather: broadcast LDG.64 of packed edge, gather LDG.128 of row
__global__ void hop_kernel(float* __restrict__ out, int in_off4, int out_off4) {
    int lane = threadIdx.x & 31;
    int node = (blockIdx.x * (blockDim.x >> 5)) + (threadIdx.x >> 5);
    if (node >= NN) return;
    int start = g_off[node], end = g_off[node + 1];
    const float4* in4 = ((const float4*)out) + in_off4;
    float4 acc = make_float4(0.f, 0.f, 0.f, 0.f);
    #pragma unroll 4
    for (int e = start; e < end; e++) {
        unsigned long long p = g_csr[e];          // uniform across warp (broadcast)
        int   radr = (int)(p & 0xffffffffu);      // row * OUTW4
        float w    = __uint_as_float((unsigned int)(p >> 32));
        float4 v = in4[radr + lane];
        acc.x += w * v.x; acc.y += w * v.y; acc.z += w * v.z; acc.w += w * v.w;
    }
    ((float4*)out)[(long long)node * OUTW4 + out_off4 + lane] = acc;
}

// broadcast mean into out[:, 4D:5D]  (index = node*160 + 128 + lane)
__global__ void bcast_kernel(float* __restrict__ out) {
    int lane = threadIdx.x & 31;
    int node = (blockIdx.x * (blockDim.x >> 5)) + (threadIdx.x >> 5);
    if (node >= NN) return;
    const float inv = 1.0f / (float)NN;
    float4 g = make_float4(g_gsum[lane * 4 + 0] * inv, g_gsum[lane * 4 + 1] * inv,
                           g_gsum[lane * 4 + 2] * inv, g_gsum[lane * 4 + 3] * inv);
    ((float4*)out)[(long long)node * OUTW4 + 128 + lane] = g;
}

// ---------------------------------------------------------------------------
extern "C" void kernel_launch(void* const* d_in, const int* in_sizes, int n_in,
                              void* d_out, int out_size) {
    const float* x  = (const float*)d_in[0];
    const int*   ei = (const int*)d_in[1];
    const float* ew = (const float*)d_in[2];
    float* out = (float*)d_out;

    zero_kernel<<<(NN + 255) / 256, 256>>>();
    deg_kernel<<<(NE + 255) / 256, 256>>>(ei, ew);
    dinv_kernel<<<(NN + 255) / 256, 256>>>();
    partial_kernel<<<NB, 256>>>();
    bscan_kernel<<<1, 256>>>();
    offsets_kernel<<<NB, 256>>>();
    scatter_kernel<<<(NE + 255) / 256, 256>>>(ei, ew);
    copy_mean_kernel<<<(196 + 7) / 8, 256>>>(x, out);   // 196 warps cover 50000 rows

    // warp per node: 8 warps/block -> 6250 blocks
    hop_kernel<<<(NN + 7) / 8, 256>>>(out,  0, 32);
    hop_kernel<<<(NN + 7) / 8, 256>>>(out, 32, 64);
    hop_kernel<<<(NN + 7) / 8, 256>>>(out, 64, 96);

    bcast_kernel<<<(NN + 7) / 8, 256>>>(out);
}

// round 6
// speedup vs baseline: 1.9096x; 1.3510x over previous
#include <cuda_runtime.h>
#include <cuda_fp16.h>

#define NN 50000
#define NE 800000
#define D 128
#define OUTW4 160        // 640 floats / 4 per output row
#define NB 196           // scan blocks: 196*256 = 50176 >= NN

// ---- scratch (__device__ globals; no allocations allowed) ----
__device__ float              g_deg[NN];        // degree, then dinv in-place
__device__ int                g_count[NN];      // in-degree edge counts
__device__ int                g_off[NN + 1];    // CSR offsets
__device__ int                g_cursor[NN];     // scatter cursors
__device__ int                g_bsum[NB];       // per-block count sums
__device__ unsigned long long g_csr[NE];        // packed: (w_bits << 32) | (row * 32)
__device__ float              g_gsum[D];        // global feature sum
__device__ __align__(16) __half g_m0[NN * D];   // fp16 mirror ping
__device__ __align__(16) __half g_m1[NN * D];   // fp16 mirror pong

// ---------------------------------------------------------------------------
__global__ void zero_kernel() {
    int i = blockIdx.x * blockDim.x + threadIdx.x;
    if (i < NN) { g_deg[i] = 0.0f; g_count[i] = 0; g_cursor[i] = 0; }
    if (i < D)  g_gsum[i] = 0.0f;
}

// edge_index is int32 (JAX demotes int64 without x64 flag)
__global__ void deg_kernel(const int* __restrict__ ei,
                           const float* __restrict__ ew) {
    int e = blockIdx.x * blockDim.x + threadIdx.x;
    if (e >= NE) return;
    int col = ei[NE + e];
    atomicAdd(&g_deg[col], ew[e]);
    atomicAdd(&g_count[col], 1);
}

// phase 1 of scan: per-block (256 contiguous counts) reduction; fused dinv
__global__ void partial_kernel() {
    int i = blockIdx.x * 256 + threadIdx.x;
    int lane = threadIdx.x & 31, wid = threadIdx.x >> 5;
    int v = 0;
    if (i < NN) {
        v = g_count[i];
        float d = g_deg[i];
        g_deg[i] = (d > 0.0f) ? rsqrtf(d) : 0.0f;    // dinv in-place
    }
    #pragma unroll
    for (int s = 16; s > 0; s >>= 1) v += __shfl_down_sync(0xffffffffu, v, s);
    __shared__ int ws[8];
    if (lane == 0) ws[wid] = v;
    __syncthreads();
    if (threadIdx.x == 0) {
        int t = 0;
        #pragma unroll
        for (int w = 0; w < 8; w++) t += ws[w];
        g_bsum[blockIdx.x] = t;
    }
}

// phase 2: exclusive scan of NB block sums
__global__ void bscan_kernel() {
    int tid = threadIdx.x;
    int v = (tid < NB) ? g_bsum[tid] : 0;
    int lane = tid & 31, wid = tid >> 5;
    int iv = v;
    #pragma unroll
    for (int s = 1; s < 32; s <<= 1) {
        int t = __shfl_up_sync(0xffffffffu, iv, s);
        if (lane >= s) iv += t;
    }
    __shared__ int wtot[8];
    if (lane == 31) wtot[wid] = iv;
    __syncthreads();
    if (wid == 0 && lane < 8) {
        int t = wtot[lane];
        #pragma unroll
        for (int s = 1; s < 8; s <<= 1) {
            int u = __shfl_up_sync(0xffu, t, s);
            if (lane >= s) t += u;
        }
        wtot[lane] = t;
    }
    __syncthreads();
    int excl = iv - v + (wid > 0 ? wtot[wid - 1] : 0);
    __syncthreads();
    if (tid < NB) g_bsum[tid] = excl;
    if (tid == 0) g_off[NN] = NE;
}

// phase 3: per-block exclusive scan of 256 counts + block prefix -> g_off
__global__ void offsets_kernel() {
    int i = blockIdx.x * 256 + threadIdx.x;
    int lane = threadIdx.x & 31, wid = threadIdx.x >> 5;
    int v = (i < NN) ? g_count[i] : 0;
    int iv = v;
    #pragma unroll
    for (int s = 1; s < 32; s <<= 1) {
        int t = __shfl_up_sync(0xffffffffu, iv, s);
        if (lane >= s) iv += t;
    }
    __shared__ int wtot[8];
    if (lane == 31) wtot[wid] = iv;
    __syncthreads();
    if (wid == 0 && lane < 8) {
        int t = wtot[lane];
        #pragma unroll
        for (int s = 1; s < 8; s <<= 1) {
            int u = __shfl_up_sync(0xffu, t, s);
            if (lane >= s) t += u;
        }
        wtot[lane] = t;
    }
    __syncthreads();
    int excl = iv - v + (wid > 0 ? wtot[wid - 1] : 0) + g_bsum[blockIdx.x];
    if (i < NN) g_off[i] = excl;
}

// scatter edges into CSR with normalized weight; addr in uint2(=4-half) units
__global__ void scatter_kernel(const int* __restrict__ ei,
                               const float* __restrict__ ew) {
    int e = blockIdx.x * blockDim.x + threadIdx.x;
    if (e >= NE) return;
    int row = ei[e];
    int col = ei[NE + e];
    float w = g_deg[row] * ew[e] * g_deg[col];
    int pos = g_off[col] + atomicAdd(&g_cursor[col], 1);
    unsigned long long p =
        ((unsigned long long)__float_as_uint(w) << 32) |
        (unsigned int)(row * 32);                    // row offset in uint2 units
    g_csr[pos] = p;
}

// copy x -> out slab0 (fp32) + fp16 mirror m0 + column-sum atomics
// one warp per 64 rows: 784 warps
__global__ void copy_mean_kernel(const float* __restrict__ x, float* __restrict__ out) {
    int lane = threadIdx.x & 31;
    int wrp  = blockIdx.x * 8 + (threadIdx.x >> 5);
    int r0 = wrp * 64;
    if (r0 >= NN) return;
    int r1 = min(r0 + 64, NN);
    const float4* x4 = (const float4*)x;
    float4* out4 = (float4*)out;
    uint2* m0 = (uint2*)g_m0;                       // device-side reference: real address
    float4 s = make_float4(0.f, 0.f, 0.f, 0.f);
    for (int r = r0; r < r1; r++) {
        float4 v = x4[r * 32 + lane];
        out4[(long long)r * OUTW4 + lane] = v;
        __half2 h0 = __floats2half2_rn(v.x, v.y);
        __half2 h1 = __floats2half2_rn(v.z, v.w);
        uint2 mv;
        mv.x = *(unsigned int*)&h0;
        mv.y = *(unsigned int*)&h1;
        m0[r * 32 + lane] = mv;
        s.x += v.x; s.y += v.y; s.z += v.z; s.w += v.w;
    }
    atomicAdd(&g_gsum[lane * 4 + 0], s.x);
    atomicAdd(&g_gsum[lane * 4 + 1], s.y);
    atomicAdd(&g_gsum[lane * 4 + 2], s.z);
    atomicAdd(&g_gsum[lane * 4 + 3], s.w);
}

// warp-per-node gather over fp16 mirror; fp32 accumulate.
// which = 0: in=m0, mir=m1 | 1: in=m1, mir=m0 | 2: in=m0, final (write mean slab)
// Mirrors are selected IN DEVICE CODE — never pass __device__ globals from host.
__global__ void hop_kernel(float* __restrict__ out, int out_off4, int which) {
    int lane = threadIdx.x & 31;
    int node = blockIdx.x * 8 + (threadIdx.x >> 5);
    if (node >= NN) return;
    const uint2* in2 = (which == 1) ? (const uint2*)g_m1 : (const uint2*)g_m0;
    int start = g_off[node], end = g_off[node + 1];
    float4 acc = make_float4(0.f, 0.f, 0.f, 0.f);
    #pragma unroll 4
    for (int e = start; e < end; e++) {
        unsigned long long p = g_csr[e];          // uniform across warp (broadcast)
        int   radr = (int)(p & 0xffffffffu);      // row * 32 (uint2 units)
        float w    = __uint_as_float((unsigned int)(p >> 32));
        uint2 v = in2[radr + lane];               // 8B gather: 4 halves
        __half2 h0 = *(__half2*)&v.x;
        __half2 h1 = *(__half2*)&v.y;
        float2 f0 = __half22float2(h0);
        float2 f1 = __half22float2(h1);
        acc.x += w * f0.x; acc.y += w * f0.y;
        acc.z += w * f1.x; acc.w += w * f1.y;
    }
    ((float4*)out)[(long long)node * OUTW4 + out_off4 + lane] = acc;
    if (which != 2) {
        uint2* mir2 = (which == 0) ? (uint2*)g_m1 : (uint2*)g_m0;
        __half2 h0 = __floats2half2_rn(acc.x, acc.y);
        __half2 h1 = __floats2half2_rn(acc.z, acc.w);
        uint2 mv;
        mv.x = *(unsigned int*)&h0;
        mv.y = *(unsigned int*)&h1;
        mir2[node * 32 + lane] = mv;
    } else {
        const float inv = 1.0f / (float)NN;
        float4 g = make_float4(g_gsum[lane * 4 + 0] * inv, g_gsum[lane * 4 + 1] * inv,
                               g_gsum[lane * 4 + 2] * inv, g_gsum[lane * 4 + 3] * inv);
        ((float4*)out)[(long long)node * OUTW4 + 128 + lane] = g;
    }
}

// ---------------------------------------------------------------------------
extern "C" void kernel_launch(void* const* d_in, const int* in_sizes, int n_in,
                              void* d_out, int out_size) {
    const float* x  = (const float*)d_in[0];
    const int*   ei = (const int*)d_in[1];
    const float* ew = (const float*)d_in[2];
    float* out = (float*)d_out;

    zero_kernel<<<(NN + 255) / 256, 256>>>();
    deg_kernel<<<(NE + 255) / 256, 256>>>(ei, ew);
    partial_kernel<<<NB, 256>>>();                 // also computes dinv
    bscan_kernel<<<1, 256>>>();
    offsets_kernel<<<NB, 256>>>();
    scatter_kernel<<<(NE + 255) / 256, 256>>>(ei, ew);
    copy_mean_kernel<<<98, 256>>>(x, out);         // 784 warps x 64 rows

    // warp per node, 8 warps/block
    hop_kernel<<<(NN + 7) / 8, 256>>>(out, 32, 0); // m0 -> slab1, mirror m1
    hop_kernel<<<(NN + 7) / 8, 256>>>(out, 64, 1); // m1 -> slab2, mirror m0
    hop_kernel<<<(NN + 7) / 8, 256>>>(out, 96, 2); // m0 -> slab3, + mean slab
}

// round 7
// speedup vs baseline: 2.0120x; 1.0536x over previous
#include <cuda_runtime.h>
#include <cuda_fp16.h>

#define NN 50000
#define NE 800000
#define D 128
#define OUTW4 160        // 640 floats / 4 per output row

// ---- scratch (__device__ globals; no allocations allowed) ----
__device__ float              g_deg[NN];        // degree, then dinv in-place
__device__ int                g_count[NN];      // in-degree edge counts
__device__ int                g_cursor[NN];     // scatter cursors
__device__ int                g_alloc;          // bump allocator
__device__ unsigned long long g_seg[NN];        // packed (cnt << 32) | start
__device__ unsigned long long g_csr[NE];        // packed (w_bits << 32) | (row * 32)
__device__ float              g_gsum[D];        // global feature sum
__device__ __align__(16) __half g_m0[NN * D];   // fp16 mirror ping
__device__ __align__(16) __half g_m1[NN * D];   // fp16 mirror pong

// ---------------------------------------------------------------------------
__global__ void zero_kernel() {
    int i = blockIdx.x * blockDim.x + threadIdx.x;
    if (i < NN) { g_deg[i] = 0.0f; g_count[i] = 0; g_cursor[i] = 0; }
    if (i < D)  g_gsum[i] = 0.0f;
    if (i == 0) g_alloc = 0;
}

// edge_index is int32 (JAX demotes int64 without x64 flag)
__global__ void deg_kernel(const int* __restrict__ ei,
                           const float* __restrict__ ew) {
    int e = blockIdx.x * blockDim.x + threadIdx.x;
    if (e >= NE) return;
    int col = ei[NE + e];
    atomicAdd(&g_deg[col], ew[e]);
    atomicAdd(&g_count[col], 1);
}

// segment allocation via warp-aggregated atomic bump; dinv fused.
// Segment bases are unordered — hop only needs [start, start+cnt) per node.
__global__ void alloc_kernel() {
    int i = blockIdx.x * 256 + threadIdx.x;
    int lane = threadIdx.x & 31;
    int cnt = 0;
    if (i < NN) {
        cnt = g_count[i];
        float d = g_deg[i];
        g_deg[i] = (d > 0.0f) ? rsqrtf(d) : 0.0f;
    }
    // inclusive warp scan of cnt
    int iv = cnt;
    #pragma unroll
    for (int s = 1; s < 32; s <<= 1) {
        int t = __shfl_up_sync(0xffffffffu, iv, s);
        if (lane >= s) iv += t;
    }
    int base = 0;
    if (lane == 31) base = atomicAdd(&g_alloc, iv);   // iv = warp total at lane 31
    base = __shfl_sync(0xffffffffu, base, 31);
    int start = base + iv - cnt;                      // exclusive prefix within warp
    if (i < NN)
        g_seg[i] = ((unsigned long long)(unsigned int)cnt << 32) |
                   (unsigned int)start;
}

// scatter edges into CSR with normalized weight; addr in uint2(=4-half) units
__global__ void scatter_kernel(const int* __restrict__ ei,
                               const float* __restrict__ ew) {
    int e = blockIdx.x * blockDim.x + threadIdx.x;
    if (e >= NE) return;
    int row = ei[e];
    int col = ei[NE + e];
    float w = g_deg[row] * ew[e] * g_deg[col];
    int start = (int)(g_seg[col] & 0xffffffffu);
    int pos = start + atomicAdd(&g_cursor[col], 1);
    unsigned long long p =
        ((unsigned long long)__float_as_uint(w) << 32) |
        (unsigned int)(row * 32);                    // row offset in uint2 units
    g_csr[pos] = p;
}

// copy x -> out slab0 (fp32) + fp16 mirror m0 + column-sum atomics
__global__ void copy_mean_kernel(const float* __restrict__ x, float* __restrict__ out) {
    int lane = threadIdx.x & 31;
    int wrp  = blockIdx.x * 8 + (threadIdx.x >> 5);
    int r0 = wrp * 64;
    if (r0 >= NN) return;
    int r1 = min(r0 + 64, NN);
    const float4* x4 = (const float4*)x;
    float4* out4 = (float4*)out;
    uint2* m0 = (uint2*)g_m0;
    float4 s = make_float4(0.f, 0.f, 0.f, 0.f);
    for (int r = r0; r < r1; r++) {
        float4 v = x4[r * 32 + lane];
        out4[(long long)r * OUTW4 + lane] = v;
        __half2 h0 = __floats2half2_rn(v.x, v.y);
        __half2 h1 = __floats2half2_rn(v.z, v.w);
        uint2 mv;
        mv.x = *(unsigned int*)&h0;
        mv.y = *(unsigned int*)&h1;
        m0[r * 32 + lane] = mv;
        s.x += v.x; s.y += v.y; s.z += v.z; s.w += v.w;
    }
    atomicAdd(&g_gsum[lane * 4 + 0], s.x);
    atomicAdd(&g_gsum[lane * 4 + 1], s.y);
    atomicAdd(&g_gsum[lane * 4 + 2], s.z);
    atomicAdd(&g_gsum[lane * 4 + 3], s.w);
}

// warp-per-node gather over fp16 mirror; fp32 accumulate; 4-edge pipeline.
// which = 0: in=m0, mir=m1 | 1: in=m1, mir=m0 | 2: in=m0, final (+ mean slab)
__global__ void hop_kernel(float* __restrict__ out, int out_off4, int which) {
    int lane = threadIdx.x & 31;
    int node = blockIdx.x * 8 + (threadIdx.x >> 5);
    if (node >= NN) return;
    const uint2* __restrict__ in2 =
        (which == 1) ? (const uint2*)g_m1 : (const uint2*)g_m0;
    unsigned long long seg = g_seg[node];
    int start = (int)(seg & 0xffffffffu);
    int cnt   = (int)(seg >> 32);
    int end   = start + cnt;
    float4 acc = make_float4(0.f, 0.f, 0.f, 0.f);

    int e = start;
    for (; e + 4 <= end; e += 4) {
        // batch the 4 broadcast CSR loads and 4 gathers -> MLP = 4
        unsigned long long p0 = g_csr[e + 0];
        unsigned long long p1 = g_csr[e + 1];
        unsigned long long p2 = g_csr[e + 2];
        unsigned long long p3 = g_csr[e + 3];
        uint2 v0 = in2[(int)(p0 & 0xffffffffu) + lane];
        uint2 v1 = in2[(int)(p1 & 0xffffffffu) + lane];
        uint2 v2 = in2[(int)(p2 & 0xffffffffu) + lane];
        uint2 v3 = in2[(int)(p3 & 0xffffffffu) + lane];
        float w0 = __uint_as_float((unsigned int)(p0 >> 32));
        float w1 = __uint_as_float((unsigned int)(p1 >> 32));
        float w2 = __uint_as_float((unsigned int)(p2 >> 32));
        float w3 = __uint_as_float((unsigned int)(p3 >> 32));
        float2 a0 = __half22float2(*(__half2*)&v0.x), b0 = __half22float2(*(__half2*)&v0.y);
        float2 a1 = __half22float2(*(__half2*)&v1.x), b1 = __half22float2(*(__half2*)&v1.y);
        float2 a2 = __half22float2(*(__half2*)&v2.x), b2 = __half22float2(*(__half2*)&v2.y);
        float2 a3 = __half22float2(*(__half2*)&v3.x), b3 = __half22float2(*(__half2*)&v3.y);
        acc.x += w0 * a0.x; acc.y += w0 * a0.y; acc.z += w0 * b0.x; acc.w += w0 * b0.y;
        acc.x += w1 * a1.x; acc.y += w1 * a1.y; acc.z += w1 * b1.x; acc.w += w1 * b1.y;
        acc.x += w2 * a2.x; acc.y += w2 * a2.y; acc.z += w2 * b2.x; acc.w += w2 * b2.y;
        acc.x += w3 * a3.x; acc.y += w3 * a3.y; acc.z += w3 * b3.x; acc.w += w3 * b3.y;
    }
    for (; e < end; e++) {
        unsigned long long p = g_csr[e];
        uint2 v = in2[(int)(p & 0xffffffffu) + lane];
        float w = __uint_as_float((unsigned int)(p >> 32));
        float2 a = __half22float2(*(__half2*)&v.x);
        float2 b = __half22float2(*(__half2*)&v.y);
        acc.x += w * a.x; acc.y += w * a.y; acc.z += w * b.x; acc.w += w * b.y;
    }

    ((float4*)out)[(long long)node * OUTW4 + out_off4 + lane] = acc;
    if (which != 2) {
        uint2* mir2 = (which == 0) ? (uint2*)g_m1 : (uint2*)g_m0;
        __half2 h0 = __floats2half2_rn(acc.x, acc.y);
        __half2 h1 = __floats2half2_rn(acc.z, acc.w);
        uint2 mv;
        mv.x = *(unsigned int*)&h0;
        mv.y = *(unsigned int*)&h1;
        mir2[node * 32 + lane] = mv;
    } else {
        const float inv = 1.0f / (float)NN;
        float4 g = make_float4(g_gsum[lane * 4 + 0] * inv, g_gsum[lane * 4 + 1] * inv,
                               g_gsum[lane * 4 + 2] * inv, g_gsum[lane * 4 + 3] * inv);
        ((float4*)out)[(long long)node * OUTW4 + 128 + lane] = g;
    }
}

// ---------------------------------------------------------------------------
extern "C" void kernel_launch(void* const* d_in, const int* in_sizes, int n_in,
                              void* d_out, int out_size) {
    const float* x  = (const float*)d_in[0];
    const int*   ei = (const int*)d_in[1];
    const float* ew = (const float*)d_in[2];
    float* out = (float*)d_out;

    zero_kernel<<<(NN + 255) / 256, 256>>>();
    deg_kernel<<<(NE + 255) / 256, 256>>>(ei, ew);
    alloc_kernel<<<(NN + 255) / 256, 256>>>();      // dinv + segment bump-alloc
    scatter_kernel<<<(NE + 255) / 256, 256>>>(ei, ew);
    copy_mean_kernel<<<98, 256>>>(x, out);          // 784 warps x 64 rows

    hop_kernel<<<(NN + 7) / 8, 256>>>(out, 32, 0);  // m0 -> slab1, mirror m1
    hop_kernel<<<(NN + 7) / 8, 256>>>(out, 64, 1);  // m1 -> slab2, mirror m0
    hop_kernel<<<(NN + 7) / 8, 256>>>(out, 96, 2);  // m0 -> slab3, + mean slab
}

// round 8
// speedup vs baseline: 2.0898x; 1.0386x over previous
#include <cuda_runtime.h>
#include <cuda_fp16.h>

#define NN 50000
#define NE 800000
#define D 128
#define OUTW4 160        // 640 floats / 4 per output row

// ---- scratch (__device__ globals; no allocations allowed) ----
__device__ unsigned long long g_pack[NN];       // (count << 40) | fixpoint32(sum w)
__device__ float              g_deg[NN];        // dinv
__device__ int                g_alloc;          // bump allocator
__device__ int                g_rank[NE];       // per-edge rank within its col
__device__ unsigned long long g_seg[NN];        // packed (cnt << 32) | start
__device__ unsigned long long g_csr[NE];        // packed (w_bits << 32) | (row * 32)
__device__ float              g_gsum[D];        // global feature sum
__device__ __align__(16) __half g_m0[NN * D];   // fp16 mirror ping
__device__ __align__(16) __half g_m1[NN * D];   // fp16 mirror pong

// ---------------------------------------------------------------------------
__global__ void zero_kernel() {
    int i = blockIdx.x * blockDim.x + threadIdx.x;
    if (i < NN) g_pack[i] = 0ull;
    if (i < D)  g_gsum[i] = 0.0f;
    if (i == 0) g_alloc = 0;
}

// ONE packed atomic per edge: degree sum (fixed point) + count; return = rank.
// edge_index is int32 (JAX demotes int64 without x64 flag)
__global__ void deg_kernel(const int* __restrict__ ei,
                           const float* __restrict__ ew) {
    int e = blockIdx.x * blockDim.x + threadIdx.x;
    if (e >= NE) return;
    int col = ei[NE + e];
    float w = ew[e];
    unsigned long long v =
        (1ull << 40) | (unsigned long long)((double)w * 4294967296.0);
    unsigned long long old = atomicAdd(&g_pack[col], v);
    g_rank[e] = (int)(old >> 40);
}

// dinv + segment bump-alloc (warp-aggregated atomic)
__global__ void alloc_kernel() {
    int i = blockIdx.x * 256 + threadIdx.x;
    int lane = threadIdx.x & 31;
    int cnt = 0;
    if (i < NN) {
        unsigned long long p = g_pack[i];
        cnt = (int)(p >> 40);
        double d = (double)(p & ((1ull << 40) - 1ull)) * (1.0 / 4294967296.0);
        g_deg[i] = (d > 0.0) ? rsqrtf((float)d) : 0.0f;
    }
    int iv = cnt;
    #pragma unroll
    for (int s = 1; s < 32; s <<= 1) {
        int t = __shfl_up_sync(0xffffffffu, iv, s);
        if (lane >= s) iv += t;
    }
    int base = 0;
    if (lane == 31) base = atomicAdd(&g_alloc, iv);
    base = __shfl_sync(0xffffffffu, base, 31);
    int start = base + iv - cnt;
    if (i < NN)
        g_seg[i] = ((unsigned long long)(unsigned int)cnt << 32) |
                   (unsigned int)start;
}

// atomic-free scatter: pos = seg.start + precomputed rank
__global__ void scatter_kernel(const int* __restrict__ ei,
                               const float* __restrict__ ew) {
    int e = blockIdx.x * blockDim.x + threadIdx.x;
    if (e >= NE) return;
    int row = ei[e];
    int col = ei[NE + e];
    float w = g_deg[row] * ew[e] * g_deg[col];
    int pos = (int)(g_seg[col] & 0xffffffffu) + g_rank[e];
    g_csr[pos] = ((unsigned long long)__float_as_uint(w) << 32) |
                 (unsigned int)(row * 32);           // row offset in uint2 units
}

// copy x -> out slab0 (fp32) + fp16 mirror m0 + column-sum atomics
__global__ void copy_mean_kernel(const float* __restrict__ x, float* __restrict__ out) {
    int lane = threadIdx.x & 31;
    int wrp  = blockIdx.x * 8 + (threadIdx.x >> 5);
    int r0 = wrp * 64;
    if (r0 >= NN) return;
    int r1 = min(r0 + 64, NN);
    const float4* x4 = (const float4*)x;
    float4* out4 = (float4*)out;
    uint2* m0 = (uint2*)g_m0;
    float4 s = make_float4(0.f, 0.f, 0.f, 0.f);
    for (int r = r0; r < r1; r++) {
        float4 v = x4[r * 32 + lane];
        out4[(long long)r * OUTW4 + lane] = v;
        __half2 h0 = __floats2half2_rn(v.x, v.y);
        __half2 h1 = __floats2half2_rn(v.z, v.w);
        uint2 mv;
        mv.x = *(unsigned int*)&h0;
        mv.y = *(unsigned int*)&h1;
        m0[r * 32 + lane] = mv;
        s.x += v.x; s.y += v.y; s.z += v.z; s.w += v.w;
    }
    atomicAdd(&g_gsum[lane * 4 + 0], s.x);
    atomicAdd(&g_gsum[lane * 4 + 1], s.y);
    atomicAdd(&g_gsum[lane * 4 + 2], s.z);
    atomicAdd(&g_gsum[lane * 4 + 3], s.w);
}

// warp-per-node gather over fp16 mirror; fp32 accumulate; 8-deep pipeline.
// which = 0: in=m0, mir=m1 | 1: in=m1, mir=m0 | 2: in=m0, final (+ mean slab)
__global__ void hop_kernel(float* __restrict__ out, int out_off4, int which) {
    int lane = threadIdx.x & 31;
    int node = blockIdx.x * 8 + (threadIdx.x >> 5);
    if (node >= NN) return;
    const uint2* __restrict__ in2 =
        (which == 1) ? (const uint2*)g_m1 : (const uint2*)g_m0;
    unsigned long long seg = g_seg[node];
    int start = (int)(seg & 0xffffffffu);
    int cnt   = (int)(seg >> 32);
    int end   = start + cnt;
    float4 acc = make_float4(0.f, 0.f, 0.f, 0.f);

    int e = start;
    for (; e + 8 <= end; e += 8) {
        unsigned long long p[8];
        uint2 v[8];
        #pragma unroll
        for (int k = 0; k < 8; k++) p[k] = __ldg(&g_csr[e + k]);
        #pragma unroll
        for (int k = 0; k < 8; k++) v[k] = __ldg(&in2[(int)(p[k] & 0xffffffffu) + lane]);
        #pragma unroll
        for (int k = 0; k < 8; k++) {
            float w = __uint_as_float((unsigned int)(p[k] >> 32));
            float2 a = __half22float2(*(__half2*)&v[k].x);
            float2 b = __half22float2(*(__half2*)&v[k].y);
            acc.x += w * a.x; acc.y += w * a.y; acc.z += w * b.x; acc.w += w * b.y;
        }
    }
    for (; e + 4 <= end; e += 4) {
        unsigned long long p[4];
        uint2 v[4];
        #pragma unroll
        for (int k = 0; k < 4; k++) p[k] = __ldg(&g_csr[e + k]);
        #pragma unroll
        for (int k = 0; k < 4; k++) v[k] = __ldg(&in2[(int)(p[k] & 0xffffffffu) + lane]);
        #pragma unroll
        for (int k = 0; k < 4; k++) {
            float w = __uint_as_float((unsigned int)(p[k] >> 32));
            float2 a = __half22float2(*(__half2*)&v[k].x);
            float2 b = __half22float2(*(__half2*)&v[k].y);
            acc.x += w * a.x; acc.y += w * a.y; acc.z += w * b.x; acc.w += w * b.y;
        }
    }
    for (; e < end; e++) {
        unsigned long long p = __ldg(&g_csr[e]);
        uint2 v = __ldg(&in2[(int)(p & 0xffffffffu) + lane]);
        float w = __uint_as_float((unsigned int)(p >> 32));
        float2 a = __half22float2(*(__half2*)&v.x);
        float2 b = __half22float2(*(__half2*)&v.y);
        acc.x += w * a.x; acc.y += w * a.y; acc.z += w * b.x; acc.w += w * b.y;
    }

    ((float4*)out)[(long long)node * OUTW4 + out_off4 + lane] = acc;
    if (which != 2) {
        uint2* mir2 = (which == 0) ? (uint2*)g_m1 : (uint2*)g_m0;
        __half2 h0 = __floats2half2_rn(acc.x, acc.y);
        __half2 h1 = __floats2half2_rn(acc.z, acc.w);
        uint2 mv;
        mv.x = *(unsigned int*)&h0;
        mv.y = *(unsigned int*)&h1;
        mir2[node * 32 + lane] = mv;
    } else {
        const float inv = 1.0f / (float)NN;
        float4 g = make_float4(g_gsum[lane * 4 + 0] * inv, g_gsum[lane * 4 + 1] * inv,
                               g_gsum[lane * 4 + 2] * inv, g_gsum[lane * 4 + 3] * inv);
        ((float4*)out)[(long long)node * OUTW4 + 128 + lane] = g;
    }
}

// ---------------------------------------------------------------------------
extern "C" void kernel_launch(void* const* d_in, const int* in_sizes, int n_in,
                              void* d_out, int out_size) {
    const float* x  = (const float*)d_in[0];
    const int*   ei = (const int*)d_in[1];
    const float* ew = (const float*)d_in[2];
    float* out = (float*)d_out;

    zero_kernel<<<(NN + 255) / 256, 256>>>();
    deg_kernel<<<(NE + 255) / 256, 256>>>(ei, ew);  // 1 packed atomic/edge + rank
    alloc_kernel<<<(NN + 255) / 256, 256>>>();      // dinv + segment bump-alloc
    scatter_kernel<<<(NE + 255) / 256, 256>>>(ei, ew);  // atomic-free
    copy_mean_kernel<<<98, 256>>>(x, out);          // 784 warps x 64 rows

    hop_kernel<<<(NN + 7) / 8, 256>>>(out, 32, 0);  // m0 -> slab1, mirror m1
    hop_kernel<<<(NN + 7) / 8, 256>>>(out, 64, 1);  // m1 -> slab2, mirror m0
    hop_kernel<<<(NN + 7) / 8, 256>>>(out, 96, 2);  // m0 -> slab3, + mean slab
}